// round 9
// baseline (speedup 1.0000x reference)
#include <cuda_runtime.h>
#include <cuda_fp16.h>
#include <math.h>

#define NN   100000
#define EE   1600000
#define DIN  128
#define HD   64      // HEADS*HID
#define HEADS 4
#define HID  16
#define DOUT 32
#define NEG  0.2f
#define NBLK ((NN + 1023) / 1024)   // scan blocks = 98
#define KC   32                      // k-chunk
#define XS_STRIDE 36
#define G1_SMEM ((DIN * HD + 128 * XS_STRIDE) * 4)   // 51200 B
#define FULLM 0xffffffffu

// ---------------- scratch (device globals; no allocation allowed) ----------
__device__ __align__(16) __half g_h1h[NN * HD];     // x @ W1   (fp16 storage)
__device__ __align__(16) float g_als1[NN * HEADS];
__device__ __align__(16) float g_ald1[NN * HEADS];
__device__ __align__(16) __half g_t2h[NN * DOUT];   // feat1 @ W2 (fp16 storage)
__device__ __align__(16) float g_als2[NN];
__device__ __align__(16) float g_ald2[NN];
// CSR scratch
__device__ __align__(16) int g_src[EE];
__device__ __align__(16) int g_dst[EE];
__device__ __align__(16) int g_rank[EE];            // per-dst arrival rank
__device__ int g_cnt[NN];
__device__ int g_indptr[NN + 1];
__device__ int g_indices[EE];
__device__ int g_bsum[NBLK];
__device__ int g_is64;

__global__ void gemm1_kernel(const float*, const float*, const float*, const float*);

// ---------------- stream/event for fork-join overlap (created pre-main) ----
static cudaStream_t g_s2;
static cudaEvent_t g_evFork, g_evJoin;
static struct Boot {
    Boot() {
        cudaStreamCreateWithFlags(&g_s2, cudaStreamNonBlocking);
        cudaEventCreateWithFlags(&g_evFork, cudaEventDisableTiming);
        cudaEventCreateWithFlags(&g_evJoin, cudaEventDisableTiming);
        cudaFuncSetAttribute(gemm1_kernel,
                             cudaFuncAttributeMaxDynamicSharedMemorySize, G1_SMEM);
    }
} g_boot;

__device__ __forceinline__ float lrelu_exp(float l) {
    l = fmaxf(l, NEG * l);                // branchless leaky relu
    return __expf(fminf(l, 25.f));        // clamp is a no-op safety net
}

// ---------------- detect dtype (1 warp) ------------------------------------
__global__ void detect_kernel(const long long* ei) {
    if (threadIdx.x == 0) {
        int ok = 1;
        for (int k = 0; k < 64; k++) {
            long long v = ei[k];
            if (v < 0 || v >= NN) { ok = 0; break; }
        }
        g_is64 = ok;
    }
}

// ---------------- convert + count + rank (2 edges/thread) ------------------
__global__ void convert_count_kernel(const long long* __restrict__ ei) {
    int e = (blockIdx.x * blockDim.x + threadIdx.x) * 2;
    if (e >= EE) return;
    int s0, s1, d0, d1;
    if (g_is64) {
        longlong2 sv = *(const longlong2*)&ei[e];
        longlong2 dv = *(const longlong2*)&ei[e + EE];
        s0 = (int)sv.x; s1 = (int)sv.y; d0 = (int)dv.x; d1 = (int)dv.y;
    } else {
        const int* p = (const int*)ei;
        int2 sv = *(const int2*)&p[e];
        int2 dv = *(const int2*)&p[e + EE];
        s0 = sv.x; s1 = sv.y; d0 = dv.x; d1 = dv.y;
    }
    *(int2*)&g_src[e] = make_int2(s0, s1);
    *(int2*)&g_dst[e] = make_int2(d0, d1);
    int r0 = atomicAdd(&g_cnt[d0], 1);
    int r1 = atomicAdd(&g_cnt[d1], 1);
    *(int2*)&g_rank[e] = make_int2(r0, r1);
}

// ---------------- scan phase 1: per-block exclusive scan -------------------
__global__ void scan1_kernel() {
    __shared__ int wsum[32];
    int t = threadIdx.x;
    int i = blockIdx.x * 1024 + t;
    int v = (i < NN) ? g_cnt[i] : 0;
    int lane = t & 31, wid = t >> 5;
    int p = v;
    #pragma unroll
    for (int off = 1; off < 32; off <<= 1) {
        int a = __shfl_up_sync(FULLM, p, off);
        if (lane >= off) p += a;
    }
    if (lane == 31) wsum[wid] = p;
    __syncthreads();
    if (wid == 0) {
        int s = wsum[lane];
        #pragma unroll
        for (int off = 1; off < 32; off <<= 1) {
            int a = __shfl_up_sync(FULLM, s, off);
            if (lane >= off) s += a;
        }
        wsum[lane] = s;
    }
    __syncthreads();
    int base = (wid > 0) ? wsum[wid - 1] : 0;
    int incl = p + base;
    if (i < NN) g_indptr[i] = incl - v;      // exclusive within block
    if (t == 1023) g_bsum[blockIdx.x] = incl;
}

// ---------------- scan phase 2+3 merged ------------------------------------
__global__ void scan23_kernel() {
    int i = blockIdx.x * blockDim.x + threadIdx.x;
    int j = (int)((blockIdx.x * blockDim.x) >> 10);
    int lane = threadIdx.x & 31;
    int acc = 0;
    for (int k = lane; k < j; k += 32) acc += g_bsum[k];
    #pragma unroll
    for (int off = 16; off > 0; off >>= 1)
        acc += __shfl_xor_sync(FULLM, acc, off);
    if (i < NN) g_indptr[i] += acc;
    if (i == 0) g_indptr[NN] = EE;
}

// ---------------- CSR scatter: pure loads/stores (rank precomputed) --------
__global__ void scatter_kernel() {
    int e = blockIdx.x * blockDim.x + threadIdx.x;
    if (e >= EE) return;
    int s = g_src[e], d = g_dst[e], r = g_rank[e];
    g_indices[g_indptr[d] + r] = s;
}

// ---------------- GEMM1 (smem W, chunked xs) + fused als1/ald1 -------------
__global__ __launch_bounds__(256, 4)
void gemm1_kernel(const float* __restrict__ x, const float* __restrict__ W,
                  const float* __restrict__ a_src, const float* __restrict__ a_dst) {
    extern __shared__ float sm[];
    float* ws = sm;                         // [128][64]
    float* xs = sm + DIN * HD;              // [128][XS_STRIDE]
    int t = threadIdx.x;
    int bn = blockIdx.x * 128;
    for (int i = t; i < DIN * HD / 4; i += 256)
        ((float4*)ws)[i] = ((const float4*)W)[i];

    int colq = t & 7;
    int nr   = t >> 3;
    float4 accA[4], accB[4];
    #pragma unroll
    for (int i = 0; i < 4; i++) {
        accA[i] = make_float4(0.f, 0.f, 0.f, 0.f);
        accB[i] = make_float4(0.f, 0.f, 0.f, 0.f);
    }
    for (int kc = 0; kc < DIN; kc += KC) {
        __syncthreads();
        #pragma unroll
        for (int i = t; i < 128 * 8; i += 256) {
            int r = i >> 3, c = i & 7;
            int node = bn + r;
            float4 v = (node < NN)
                ? *(const float4*)&x[(size_t)node * DIN + kc + c * 4]
                : make_float4(0.f, 0.f, 0.f, 0.f);
            *(float4*)&xs[r * XS_STRIDE + c * 4] = v;
        }
        __syncthreads();
        #pragma unroll 8
        for (int kk = 0; kk < KC; kk++) {
            float4 wa = *(const float4*)&ws[(kc + kk) * HD + colq * 4];
            float4 wb = *(const float4*)&ws[(kc + kk) * HD + 32 + colq * 4];
            float x0 = xs[nr * XS_STRIDE + kk];
            float x1 = xs[(nr + 32) * XS_STRIDE + kk];
            float x2 = xs[(nr + 64) * XS_STRIDE + kk];
            float x3 = xs[(nr + 96) * XS_STRIDE + kk];
            accA[0].x += x0*wa.x; accA[0].y += x0*wa.y; accA[0].z += x0*wa.z; accA[0].w += x0*wa.w;
            accB[0].x += x0*wb.x; accB[0].y += x0*wb.y; accB[0].z += x0*wb.z; accB[0].w += x0*wb.w;
            accA[1].x += x1*wa.x; accA[1].y += x1*wa.y; accA[1].z += x1*wa.z; accA[1].w += x1*wa.w;
            accB[1].x += x1*wb.x; accB[1].y += x1*wb.y; accB[1].z += x1*wb.z; accB[1].w += x1*wb.w;
            accA[2].x += x2*wa.x; accA[2].y += x2*wa.y; accA[2].z += x2*wa.z; accA[2].w += x2*wa.w;
            accB[2].x += x2*wb.x; accB[2].y += x2*wb.y; accB[2].z += x2*wb.z; accB[2].w += x2*wb.w;
            accA[3].x += x3*wa.x; accA[3].y += x3*wa.y; accA[3].z += x3*wa.z; accA[3].w += x3*wa.w;
            accB[3].x += x3*wb.x; accB[3].y += x3*wb.y; accB[3].z += x3*wb.z; accB[3].w += x3*wb.w;
        }
    }
    int hA = colq >> 2;
    int hB = 2 + hA;
    int woff = (colq & 3) * 4;
    float4 sA = *(const float4*)&a_src[hA * HID + woff];
    float4 dA = *(const float4*)&a_dst[hA * HID + woff];
    float4 sB = *(const float4*)&a_src[hB * HID + woff];
    float4 dB = *(const float4*)&a_dst[hB * HID + woff];
    #pragma unroll
    for (int i = 0; i < 4; i++) {
        int node = bn + nr + i * 32;
        bool ok = node < NN;
        if (ok) {
            __half2 pa0 = __floats2half2_rn(accA[i].x, accA[i].y);
            __half2 pa1 = __floats2half2_rn(accA[i].z, accA[i].w);
            __half2 pb0 = __floats2half2_rn(accB[i].x, accB[i].y);
            __half2 pb1 = __floats2half2_rn(accB[i].z, accB[i].w);
            *(uint2*)&g_h1h[(size_t)node * HD + colq * 4]      = make_uint2(*(unsigned*)&pa0, *(unsigned*)&pa1);
            *(uint2*)&g_h1h[(size_t)node * HD + 32 + colq * 4] = make_uint2(*(unsigned*)&pb0, *(unsigned*)&pb1);
        }
        float psA = accA[i].x*sA.x + accA[i].y*sA.y + accA[i].z*sA.z + accA[i].w*sA.w;
        float pdA = accA[i].x*dA.x + accA[i].y*dA.y + accA[i].z*dA.z + accA[i].w*dA.w;
        float psB = accB[i].x*sB.x + accB[i].y*sB.y + accB[i].z*sB.z + accB[i].w*sB.w;
        float pdB = accB[i].x*dB.x + accB[i].y*dB.y + accB[i].z*dB.z + accB[i].w*dB.w;
        #pragma unroll
        for (int off = 1; off < 4; off <<= 1) {
            psA += __shfl_xor_sync(FULLM, psA, off);
            pdA += __shfl_xor_sync(FULLM, pdA, off);
            psB += __shfl_xor_sync(FULLM, psB, off);
            pdB += __shfl_xor_sync(FULLM, pdB, off);
        }
        if (((colq & 3) == 0) && ok) {
            g_als1[node * 4 + hA] = psA;
            g_ald1[node * 4 + hA] = pdA;
            g_als1[node * 4 + hB] = psB;
            g_ald1[node * 4 + hB] = pdB;
        }
    }
}

// ---------------- FUSED gather1: coalesced idx prefetch + shfl distribute --
__global__ void gather1_fused_kernel(const float* __restrict__ b1,
                                     const float* __restrict__ W2,
                                     const float* __restrict__ a_src2,
                                     const float* __restrict__ a_dst2) {
    int n = (blockIdx.x * blockDim.x + threadIdx.x) >> 5;
    if (n >= NN) return;
    int lane = threadIdx.x & 31;
    int h = lane >> 3;
    float ad = g_ald1[n * 4 + h];
    float accx = 0.f, accy = 0.f, z = 0.f;
    { // self loop
        float w = lrelu_exp(g_als1[n * 4 + h] + ad);
        z += w;
        __half2 v = ((const __half2*)&g_h1h[(size_t)n * HD])[lane];
        float2 vf = __half22float2(v);
        accx += vf.x * w; accy += vf.y * w;
    }
    int beg = g_indptr[n], end = g_indptr[n + 1];
    for (int base = beg; base < end; base += 32) {
        int cnt = min(32, end - base);
        int myidx = (base + lane < end) ? g_indices[base + lane] : 0;  // 1 coalesced LDG / 32 edges
        int j = 0;
        for (; j + 8 <= cnt; j += 8) {
            int s[8]; float l[8]; __half2 v[8];
            #pragma unroll
            for (int q = 0; q < 8; q++) s[q] = __shfl_sync(FULLM, myidx, j + q);
            #pragma unroll
            for (int q = 0; q < 8; q++) l[q] = g_als1[s[q] * 4 + h];
            #pragma unroll
            for (int q = 0; q < 8; q++) v[q] = ((const __half2*)&g_h1h[(size_t)s[q] * HD])[lane];
            #pragma unroll
            for (int q = 0; q < 8; q++) {
                float w = lrelu_exp(l[q] + ad);
                z += w;
                float2 vf = __half22float2(v[q]);
                accx += vf.x * w; accy += vf.y * w;
            }
        }
        for (; j < cnt; j++) {
            int s = __shfl_sync(FULLM, myidx, j);
            float w = lrelu_exp(g_als1[s * 4 + h] + ad);
            z += w;
            __half2 v = ((const __half2*)&g_h1h[(size_t)s * HD])[lane];
            float2 vf = __half22float2(v);
            accx += vf.x * w; accy += vf.y * w;
        }
    }
    float zi = 1.f / (z + 1e-16f);
    float2 bb = ((const float2*)b1)[lane];
    float vx = accx * zi + bb.x;
    float vy = accy * zi + bb.y;
    vx = vx > 0.f ? vx : expm1f(vx);    // ELU
    vy = vy > 0.f ? vy : expm1f(vy);
    // ---- fused GEMV: t = feat @ W2, lane computes output channel `lane` ----
    float t = 0.f;
    #pragma unroll
    for (int k = 0; k < 32; k++) {
        float fx = __shfl_sync(FULLM, vx, k);
        float fy = __shfl_sync(FULLM, vy, k);
        t += fx * __ldg(&W2[(2 * k) * DOUT + lane])
           + fy * __ldg(&W2[(2 * k + 1) * DOUT + lane]);
    }
    g_t2h[(size_t)n * DOUT + lane] = __float2half_rn(t);
    // ---- fused als2/ald2 (fp32 exact) ----
    float ps = t * __ldg(&a_src2[lane]);
    float pd = t * __ldg(&a_dst2[lane]);
    #pragma unroll
    for (int off = 16; off > 0; off >>= 1) {
        ps += __shfl_xor_sync(FULLM, ps, off);
        pd += __shfl_xor_sync(FULLM, pd, off);
    }
    if (lane == 0) { g_als2[n] = ps; g_ald2[n] = pd; }
}

// ---------------- gather2: coalesced idx prefetch + shfl distribute --------
__global__ void gather2_kernel(float* __restrict__ out, const float* __restrict__ b2) {
    int n = (blockIdx.x * blockDim.x + threadIdx.x) >> 5;
    if (n >= NN) return;
    int lane = threadIdx.x & 31;
    float ad = g_ald2[n];
    float acc = 0.f, z = 0.f;
    { // self loop
        float w = lrelu_exp(g_als2[n] + ad);
        z += w;
        acc += __half2float(g_t2h[(size_t)n * DOUT + lane]) * w;
    }
    int beg = g_indptr[n], end = g_indptr[n + 1];
    for (int base = beg; base < end; base += 32) {
        int cnt = min(32, end - base);
        int myidx = (base + lane < end) ? g_indices[base + lane] : 0;
        int j = 0;
        for (; j + 8 <= cnt; j += 8) {
            int s[8]; float l[8]; __half v[8];
            #pragma unroll
            for (int q = 0; q < 8; q++) s[q] = __shfl_sync(FULLM, myidx, j + q);
            #pragma unroll
            for (int q = 0; q < 8; q++) l[q] = g_als2[s[q]];
            #pragma unroll
            for (int q = 0; q < 8; q++) v[q] = g_t2h[(size_t)s[q] * DOUT + lane];
            #pragma unroll
            for (int q = 0; q < 8; q++) {
                float w = lrelu_exp(l[q] + ad);
                z += w;
                acc += __half2float(v[q]) * w;
            }
        }
        for (; j < cnt; j++) {
            int s = __shfl_sync(FULLM, myidx, j);
            float w = lrelu_exp(g_als2[s] + ad);
            z += w;
            acc += __half2float(g_t2h[(size_t)s * DOUT + lane]) * w;
        }
    }
    out[(size_t)n * DOUT + lane] = acc / (z + 1e-16f) + b2[lane];
}

// ---------------------------------------------------------------------------
extern "C" void kernel_launch(void* const* d_in, const int* in_sizes, int n_in,
                              void* d_out, int out_size) {
    const float*     x      = (const float*)d_in[0];
    const long long* ei     = (const long long*)d_in[1];
    const float*     W1     = (const float*)d_in[2];
    const float*     a_src1 = (const float*)d_in[3];
    const float*     a_dst1 = (const float*)d_in[4];
    const float*     b1     = (const float*)d_in[5];
    const float*     W2     = (const float*)d_in[6];
    const float*     a_src2 = (const float*)d_in[7];
    const float*     a_dst2 = (const float*)d_in[8];
    const float*     b2     = (const float*)d_in[9];
    float* out = (float*)d_out;

    const int NB = (NN + 255) / 256;
    const int GB = (NN + 127) / 128;
    const int EB = (EE + 255) / 256;
    const int E2 = (EE / 2 + 255) / 256;
    const int WB = (NN * 32 + 255) / 256;

    // zero degree counters via memset node (not a kernel launch)
    void* cntPtr = nullptr;
    cudaGetSymbolAddress(&cntPtr, g_cnt);
    cudaMemsetAsync(cntPtr, 0, NN * sizeof(int), 0);

    cudaEventRecord(g_evFork, 0);
    cudaStreamWaitEvent(g_s2, g_evFork, 0);

    detect_kernel<<<1, 32>>>(ei);
    convert_count_kernel<<<E2, 256>>>(ei);
    scan1_kernel<<<NBLK, 1024>>>();
    gemm1_kernel<<<GB, 256, G1_SMEM, g_s2>>>(x, W1, a_src1, a_dst1);
    cudaEventRecord(g_evJoin, g_s2);
    scan23_kernel<<<NB, 256>>>();
    scatter_kernel<<<EB, 256>>>();

    cudaStreamWaitEvent(0, g_evJoin, 0);
    gather1_fused_kernel<<<WB, 256>>>(b1, W2, a_src2, a_dst2);
    gather2_kernel<<<WB, 256>>>(out, b2);
}

// round 10
// speedup vs baseline: 1.0471x; 1.0471x over previous
#include <cuda_runtime.h>
#include <cuda_fp16.h>
#include <math.h>

#define NN   100000
#define EE   1600000
#define DIN  128
#define HD   64      // HEADS*HID
#define HEADS 4
#define HID  16
#define DOUT 32
#define NEG  0.2f
#define NBLK ((NN + 1023) / 1024)   // scan blocks = 98
#define KC   32                      // k-chunk
#define XS_STRIDE 36
#define G1_SMEM ((DIN * HD + 128 * XS_STRIDE) * 4)   // 51200 B
#define FULLM 0xffffffffu

typedef unsigned long long u64;

// ---------------- scratch (device globals; no allocation allowed) ----------
__device__ __align__(16) __half g_h1h[NN * HD];     // x @ W1   (fp16 storage)
__device__ __align__(16) float g_als1[NN * HEADS];
__device__ __align__(16) float g_ald1[NN * HEADS];
__device__ __align__(16) __half g_t2h[NN * DOUT];   // feat1 @ W2 (fp16 storage)
__device__ __align__(16) float g_als2[NN];
__device__ __align__(16) float g_ald2[NN];
// CSR scratch
__device__ __align__(16) int g_src[EE];
__device__ __align__(16) int g_dst[EE];
__device__ __align__(16) int g_rank[EE];            // per-dst arrival rank
__device__ int g_cnt[NN];
__device__ int g_indptr[NN + 1];
__device__ int g_indices[EE];
__device__ int g_bsum[NBLK];
__device__ int g_is64;

__global__ void gemm1_kernel(const float*, const float*, const float*, const float*);

// ---------------- stream/event for fork-join overlap (created pre-main) ----
static cudaStream_t g_s2;
static cudaEvent_t g_evFork, g_evJoin;
static struct Boot {
    Boot() {
        cudaStreamCreateWithFlags(&g_s2, cudaStreamNonBlocking);
        cudaEventCreateWithFlags(&g_evFork, cudaEventDisableTiming);
        cudaEventCreateWithFlags(&g_evJoin, cudaEventDisableTiming);
        cudaFuncSetAttribute(gemm1_kernel,
                             cudaFuncAttributeMaxDynamicSharedMemorySize, G1_SMEM);
    }
} g_boot;

__device__ __forceinline__ float lrelu_exp(float l) {
    l = fmaxf(l, NEG * l);                // branchless leaky relu
    return __expf(fminf(l, 25.f));        // clamp is a no-op safety net
}

// ---- packed fp32x2 helpers (sm_103a FFMA2 path; exact fp32 rounding) ------
__device__ __forceinline__ u64 packf2(float a, float b) {
    u64 r; asm("mov.b64 %0, {%1, %2};" : "=l"(r) : "f"(a), "f"(b)); return r;
}
__device__ __forceinline__ void ffma2(u64& d, u64 a, u64 b) {
    asm("fma.rn.f32x2 %0, %1, %2, %0;" : "+l"(d) : "l"(a), "l"(b));
}
__device__ __forceinline__ float2 unpackf2(u64 v) {
    float2 r; asm("mov.b64 {%0, %1}, %2;" : "=f"(r.x), "=f"(r.y) : "l"(v)); return r;
}

// ---------------- detect dtype (1 warp) ------------------------------------
__global__ void detect_kernel(const long long* ei) {
    if (threadIdx.x == 0) {
        int ok = 1;
        for (int k = 0; k < 64; k++) {
            long long v = ei[k];
            if (v < 0 || v >= NN) { ok = 0; break; }
        }
        g_is64 = ok;
    }
}

// ---------------- convert + count + rank (2 edges/thread) ------------------
__global__ void convert_count_kernel(const long long* __restrict__ ei) {
    int e = (blockIdx.x * blockDim.x + threadIdx.x) * 2;
    if (e >= EE) return;
    int s0, s1, d0, d1;
    if (g_is64) {
        longlong2 sv = *(const longlong2*)&ei[e];
        longlong2 dv = *(const longlong2*)&ei[e + EE];
        s0 = (int)sv.x; s1 = (int)sv.y; d0 = (int)dv.x; d1 = (int)dv.y;
    } else {
        const int* p = (const int*)ei;
        int2 sv = *(const int2*)&p[e];
        int2 dv = *(const int2*)&p[e + EE];
        s0 = sv.x; s1 = sv.y; d0 = dv.x; d1 = dv.y;
    }
    *(int2*)&g_src[e] = make_int2(s0, s1);
    *(int2*)&g_dst[e] = make_int2(d0, d1);
    int r0 = atomicAdd(&g_cnt[d0], 1);
    int r1 = atomicAdd(&g_cnt[d1], 1);
    *(int2*)&g_rank[e] = make_int2(r0, r1);
}

// ---------------- scan phase 1: per-block exclusive scan -------------------
__global__ void scan1_kernel() {
    __shared__ int wsum[32];
    int t = threadIdx.x;
    int i = blockIdx.x * 1024 + t;
    int v = (i < NN) ? g_cnt[i] : 0;
    int lane = t & 31, wid = t >> 5;
    int p = v;
    #pragma unroll
    for (int off = 1; off < 32; off <<= 1) {
        int a = __shfl_up_sync(FULLM, p, off);
        if (lane >= off) p += a;
    }
    if (lane == 31) wsum[wid] = p;
    __syncthreads();
    if (wid == 0) {
        int s = wsum[lane];
        #pragma unroll
        for (int off = 1; off < 32; off <<= 1) {
            int a = __shfl_up_sync(FULLM, s, off);
            if (lane >= off) s += a;
        }
        wsum[lane] = s;
    }
    __syncthreads();
    int base = (wid > 0) ? wsum[wid - 1] : 0;
    int incl = p + base;
    if (i < NN) g_indptr[i] = incl - v;      // exclusive within block
    if (t == 1023) g_bsum[blockIdx.x] = incl;
}

// ---------------- scan phase 2+3 merged ------------------------------------
__global__ void scan23_kernel() {
    int i = blockIdx.x * blockDim.x + threadIdx.x;
    int j = (int)((blockIdx.x * blockDim.x) >> 10);
    int lane = threadIdx.x & 31;
    int acc = 0;
    for (int k = lane; k < j; k += 32) acc += g_bsum[k];
    #pragma unroll
    for (int off = 16; off > 0; off >>= 1)
        acc += __shfl_xor_sync(FULLM, acc, off);
    if (i < NN) g_indptr[i] += acc;
    if (i == 0) g_indptr[NN] = EE;
}

// ---------------- CSR scatter: 2 edges/thread, rank precomputed ------------
__global__ void scatter_kernel() {
    int e = (blockIdx.x * blockDim.x + threadIdx.x) * 2;
    if (e >= EE) return;
    int2 s = *(const int2*)&g_src[e];
    int2 d = *(const int2*)&g_dst[e];
    int2 r = *(const int2*)&g_rank[e];
    g_indices[g_indptr[d.x] + r.x] = s.x;
    g_indices[g_indptr[d.y] + r.y] = s.y;
}

// ---------------- GEMM1 (smem W, chunked xs, packed FFMA2) + als1/ald1 -----
__global__ __launch_bounds__(256, 4)
void gemm1_kernel(const float* __restrict__ x, const float* __restrict__ W,
                  const float* __restrict__ a_src, const float* __restrict__ a_dst) {
    extern __shared__ float sm[];
    float* ws = sm;                         // [128][64]
    float* xs = sm + DIN * HD;              // [128][XS_STRIDE]
    int t = threadIdx.x;
    int bn = blockIdx.x * 128;
    for (int i = t; i < DIN * HD / 4; i += 256)
        ((float4*)ws)[i] = ((const float4*)W)[i];

    int colq = t & 7;
    int nr   = t >> 3;
    // accumulators: [node][colpair]  (A = cols colq*4..+3, B = cols 32+colq*4..+3)
    u64 accA[4][2], accB[4][2];
    #pragma unroll
    for (int i = 0; i < 4; i++) {
        accA[i][0] = accA[i][1] = 0ULL;
        accB[i][0] = accB[i][1] = 0ULL;
    }
    for (int kc = 0; kc < DIN; kc += KC) {
        __syncthreads();
        #pragma unroll
        for (int i = t; i < 128 * 8; i += 256) {
            int r = i >> 3, c = i & 7;
            int node = bn + r;
            float4 v = (node < NN)
                ? *(const float4*)&x[(size_t)node * DIN + kc + c * 4]
                : make_float4(0.f, 0.f, 0.f, 0.f);
            *(float4*)&xs[r * XS_STRIDE + c * 4] = v;
        }
        __syncthreads();
        #pragma unroll 8
        for (int kk = 0; kk < KC; kk++) {
            ulonglong2 wa = *(const ulonglong2*)&ws[(kc + kk) * HD + colq * 4];
            ulonglong2 wb = *(const ulonglong2*)&ws[(kc + kk) * HD + 32 + colq * 4];
            float x0 = xs[nr * XS_STRIDE + kk];
            float x1 = xs[(nr + 32) * XS_STRIDE + kk];
            float x2 = xs[(nr + 64) * XS_STRIDE + kk];
            float x3 = xs[(nr + 96) * XS_STRIDE + kk];
            u64 X0 = packf2(x0, x0), X1 = packf2(x1, x1);
            u64 X2 = packf2(x2, x2), X3 = packf2(x3, x3);
            ffma2(accA[0][0], X0, wa.x); ffma2(accA[0][1], X0, wa.y);
            ffma2(accB[0][0], X0, wb.x); ffma2(accB[0][1], X0, wb.y);
            ffma2(accA[1][0], X1, wa.x); ffma2(accA[1][1], X1, wa.y);
            ffma2(accB[1][0], X1, wb.x); ffma2(accB[1][1], X1, wb.y);
            ffma2(accA[2][0], X2, wa.x); ffma2(accA[2][1], X2, wa.y);
            ffma2(accB[2][0], X2, wb.x); ffma2(accB[2][1], X2, wb.y);
            ffma2(accA[3][0], X3, wa.x); ffma2(accA[3][1], X3, wa.y);
            ffma2(accB[3][0], X3, wb.x); ffma2(accB[3][1], X3, wb.y);
        }
    }
    int hA = colq >> 2;
    int hB = 2 + hA;
    int woff = (colq & 3) * 4;
    float4 sA = *(const float4*)&a_src[hA * HID + woff];
    float4 dA = *(const float4*)&a_dst[hA * HID + woff];
    float4 sB = *(const float4*)&a_src[hB * HID + woff];
    float4 dB = *(const float4*)&a_dst[hB * HID + woff];
    #pragma unroll
    for (int i = 0; i < 4; i++) {
        int node = bn + nr + i * 32;
        bool ok = node < NN;
        float2 a01 = unpackf2(accA[i][0]);
        float2 a23 = unpackf2(accA[i][1]);
        float2 b01 = unpackf2(accB[i][0]);
        float2 b23 = unpackf2(accB[i][1]);
        if (ok) {
            __half2 pa0 = __floats2half2_rn(a01.x, a01.y);
            __half2 pa1 = __floats2half2_rn(a23.x, a23.y);
            __half2 pb0 = __floats2half2_rn(b01.x, b01.y);
            __half2 pb1 = __floats2half2_rn(b23.x, b23.y);
            *(uint2*)&g_h1h[(size_t)node * HD + colq * 4]      = make_uint2(*(unsigned*)&pa0, *(unsigned*)&pa1);
            *(uint2*)&g_h1h[(size_t)node * HD + 32 + colq * 4] = make_uint2(*(unsigned*)&pb0, *(unsigned*)&pb1);
        }
        float psA = a01.x*sA.x + a01.y*sA.y + a23.x*sA.z + a23.y*sA.w;
        float pdA = a01.x*dA.x + a01.y*dA.y + a23.x*dA.z + a23.y*dA.w;
        float psB = b01.x*sB.x + b01.y*sB.y + b23.x*sB.z + b23.y*sB.w;
        float pdB = b01.x*dB.x + b01.y*dB.y + b23.x*dB.z + b23.y*dB.w;
        #pragma unroll
        for (int off = 1; off < 4; off <<= 1) {
            psA += __shfl_xor_sync(FULLM, psA, off);
            pdA += __shfl_xor_sync(FULLM, pdA, off);
            psB += __shfl_xor_sync(FULLM, psB, off);
            pdB += __shfl_xor_sync(FULLM, pdB, off);
        }
        if (((colq & 3) == 0) && ok) {
            g_als1[node * 4 + hA] = psA;
            g_ald1[node * 4 + hA] = pdA;
            g_als1[node * 4 + hB] = psB;
            g_ald1[node * 4 + hB] = pdB;
        }
    }
}

// ---------------- FUSED: gather1 + ELU + (feat @ W2) + als2/ald2 (R8 form) -
__global__ void gather1_fused_kernel(const float* __restrict__ b1,
                                     const float* __restrict__ W2,
                                     const float* __restrict__ a_src2,
                                     const float* __restrict__ a_dst2) {
    int n = (blockIdx.x * blockDim.x + threadIdx.x) >> 5;
    if (n >= NN) return;
    int lane = threadIdx.x & 31;
    int h = lane >> 3;
    float ad = g_ald1[n * 4 + h];
    float accx = 0.f, accy = 0.f, z = 0.f;
    { // self loop
        float w = lrelu_exp(g_als1[n * 4 + h] + ad);
        z += w;
        __half2 v = ((const __half2*)&g_h1h[(size_t)n * HD])[lane];
        float2 vf = __half22float2(v);
        accx += vf.x * w; accy += vf.y * w;
    }
    int e = g_indptr[n], end = g_indptr[n + 1];
    for (; e + 8 <= end; e += 8) {
        int s[8]; float l[8]; __half2 v[8];
        #pragma unroll
        for (int j = 0; j < 8; j++) s[j] = g_indices[e + j];
        #pragma unroll
        for (int j = 0; j < 8; j++) l[j] = g_als1[s[j] * 4 + h];
        #pragma unroll
        for (int j = 0; j < 8; j++) v[j] = ((const __half2*)&g_h1h[(size_t)s[j] * HD])[lane];
        #pragma unroll
        for (int j = 0; j < 8; j++) {
            float w = lrelu_exp(l[j] + ad);
            z += w;
            float2 vf = __half22float2(v[j]);
            accx += vf.x * w; accy += vf.y * w;
        }
    }
    for (; e < end; e++) {
        int s = g_indices[e];
        float w = lrelu_exp(g_als1[s * 4 + h] + ad);
        z += w;
        __half2 v = ((const __half2*)&g_h1h[(size_t)s * HD])[lane];
        float2 vf = __half22float2(v);
        accx += vf.x * w; accy += vf.y * w;
    }
    float zi = 1.f / (z + 1e-16f);
    float2 bb = ((const float2*)b1)[lane];
    float vx = accx * zi + bb.x;
    float vy = accy * zi + bb.y;
    vx = vx > 0.f ? vx : expm1f(vx);    // ELU
    vy = vy > 0.f ? vy : expm1f(vy);
    // ---- fused GEMV: t = feat @ W2, lane computes output channel `lane` ----
    float t = 0.f;
    #pragma unroll
    for (int k = 0; k < 32; k++) {
        float fx = __shfl_sync(FULLM, vx, k);
        float fy = __shfl_sync(FULLM, vy, k);
        t += fx * __ldg(&W2[(2 * k) * DOUT + lane])
           + fy * __ldg(&W2[(2 * k + 1) * DOUT + lane]);
    }
    g_t2h[(size_t)n * DOUT + lane] = __float2half_rn(t);
    // ---- fused als2/ald2 (fp32 exact) ----
    float ps = t * __ldg(&a_src2[lane]);
    float pd = t * __ldg(&a_dst2[lane]);
    #pragma unroll
    for (int off = 16; off > 0; off >>= 1) {
        ps += __shfl_xor_sync(FULLM, ps, off);
        pd += __shfl_xor_sync(FULLM, pd, off);
    }
    if (lane == 0) { g_als2[n] = ps; g_ald2[n] = pd; }
}

// ---------------- layer-2 gather (R8 form): 8-wide, fp16 feats -------------
__global__ void gather2_kernel(float* __restrict__ out, const float* __restrict__ b2) {
    int n = (blockIdx.x * blockDim.x + threadIdx.x) >> 5;
    if (n >= NN) return;
    int lane = threadIdx.x & 31;
    float ad = g_ald2[n];
    float acc = 0.f, z = 0.f;
    { // self loop
        float w = lrelu_exp(g_als2[n] + ad);
        z += w;
        acc += __half2float(g_t2h[(size_t)n * DOUT + lane]) * w;
    }
    int e = g_indptr[n], end = g_indptr[n + 1];
    for (; e + 8 <= end; e += 8) {
        int s[8]; float l[8]; __half v[8];
        #pragma unroll
        for (int j = 0; j < 8; j++) s[j] = g_indices[e + j];
        #pragma unroll
        for (int j = 0; j < 8; j++) l[j] = g_als2[s[j]];
        #pragma unroll
        for (int j = 0; j < 8; j++) v[j] = g_t2h[(size_t)s[j] * DOUT + lane];
        #pragma unroll
        for (int j = 0; j < 8; j++) {
            float w = lrelu_exp(l[j] + ad);
            z += w;
            acc += __half2float(v[j]) * w;
        }
    }
    for (; e < end; e++) {
        int s = g_indices[e];
        float w = lrelu_exp(g_als2[s] + ad);
        z += w;
        acc += __half2float(g_t2h[(size_t)s * DOUT + lane]) * w;
    }
    out[(size_t)n * DOUT + lane] = acc / (z + 1e-16f) + b2[lane];
}

// ---------------------------------------------------------------------------
extern "C" void kernel_launch(void* const* d_in, const int* in_sizes, int n_in,
                              void* d_out, int out_size) {
    const float*     x      = (const float*)d_in[0];
    const long long* ei     = (const long long*)d_in[1];
    const float*     W1     = (const float*)d_in[2];
    const float*     a_src1 = (const float*)d_in[3];
    const float*     a_dst1 = (const float*)d_in[4];
    const float*     b1     = (const float*)d_in[5];
    const float*     W2     = (const float*)d_in[6];
    const float*     a_src2 = (const float*)d_in[7];
    const float*     a_dst2 = (const float*)d_in[8];
    const float*     b2     = (const float*)d_in[9];
    float* out = (float*)d_out;

    const int NB = (NN + 255) / 256;
    const int GB = (NN + 127) / 128;
    const int E2 = (EE / 2 + 255) / 256;
    const int WB = (NN * 32 + 255) / 256;

    // zero degree counters via memset node (not a kernel launch)
    void* cntPtr = nullptr;
    cudaGetSymbolAddress(&cntPtr, g_cnt);
    cudaMemsetAsync(cntPtr, 0, NN * sizeof(int), 0);

    cudaEventRecord(g_evFork, 0);
    cudaStreamWaitEvent(g_s2, g_evFork, 0);

    detect_kernel<<<1, 32>>>(ei);
    convert_count_kernel<<<E2, 256>>>(ei);
    scan1_kernel<<<NBLK, 1024>>>();
    gemm1_kernel<<<GB, 256, G1_SMEM, g_s2>>>(x, W1, a_src1, a_dst1);
    cudaEventRecord(g_evJoin, g_s2);
    scan23_kernel<<<NB, 256>>>();
    scatter_kernel<<<E2, 256>>>();

    cudaStreamWaitEvent(0, g_evJoin, 0);
    gather1_fused_kernel<<<WB, 256>>>(b1, W2, a_src2, a_dst2);
    gather2_kernel<<<WB, 256>>>(out, b2);
}

// round 11
// speedup vs baseline: 1.1219x; 1.0715x over previous
#include <cuda_runtime.h>
#include <cuda_fp16.h>
#include <math.h>

#define NN   100000
#define EE   1600000
#define DIN  128
#define HD   64      // HEADS*HID
#define HEADS 4
#define HID  16
#define DOUT 32
#define NEG  0.2f
#define NBLK ((NN + 1023) / 1024)   // scan blocks = 98
#define KC   32                      // k-chunk
#define XS_STRIDE 36
#define G1_SMEM ((DIN * HD + 128 * XS_STRIDE) * 4)   // 51200 B
#define FULLM 0xffffffffu

typedef unsigned long long u64;

// ---------------- scratch (device globals; no allocation allowed) ----------
__device__ __align__(16) __half g_h1h[NN * HD];     // x @ W1   (fp16 storage)
__device__ __align__(16) float g_als1[NN * HEADS];
__device__ __align__(16) float g_ald1[NN * HEADS];
__device__ __align__(16) __half g_t2h[NN * DOUT];   // feat1 @ W2 (fp16 storage)
__device__ __align__(16) float g_als2[NN];
__device__ __align__(16) float g_ald2[NN];
// CSR scratch
__device__ __align__(16) int g_src[EE];
__device__ __align__(16) int g_dst[EE];
__device__ __align__(16) int g_rank[EE];            // per-dst arrival rank
__device__ int g_cnt[NN];
__device__ int g_indptr[NN + 1];
__device__ int g_indices[EE];
__device__ int g_bsum[NBLK];
__device__ int g_is64;

__global__ void gemm1_kernel(const float*, const float*, const float*, const float*);

// ---------------- stream/event for fork-join overlap (created pre-main) ----
static cudaStream_t g_s2;
static cudaEvent_t g_evFork, g_evJoin;
static struct Boot {
    Boot() {
        cudaStreamCreateWithFlags(&g_s2, cudaStreamNonBlocking);
        cudaEventCreateWithFlags(&g_evFork, cudaEventDisableTiming);
        cudaEventCreateWithFlags(&g_evJoin, cudaEventDisableTiming);
        cudaFuncSetAttribute(gemm1_kernel,
                             cudaFuncAttributeMaxDynamicSharedMemorySize, G1_SMEM);
    }
} g_boot;

__device__ __forceinline__ float lrelu_exp(float l) {
    l = fmaxf(l, NEG * l);                // branchless leaky relu
    return __expf(fminf(l, 25.f));        // clamp is a no-op safety net
}

// ---- packed fp32x2 helpers (sm_103a FFMA2 path; exact fp32 rounding) ------
__device__ __forceinline__ u64 packf2(float a, float b) {
    u64 r; asm("mov.b64 %0, {%1, %2};" : "=l"(r) : "f"(a), "f"(b)); return r;
}
__device__ __forceinline__ void ffma2(u64& d, u64 a, u64 b) {
    asm("fma.rn.f32x2 %0, %1, %2, %0;" : "+l"(d) : "l"(a), "l"(b));
}
__device__ __forceinline__ float2 unpackf2(u64 v) {
    float2 r; asm("mov.b64 {%0, %1}, %2;" : "=f"(r.x), "=f"(r.y) : "l"(v)); return r;
}

// ---------------- detect dtype (1 warp) ------------------------------------
__global__ void detect_kernel(const long long* ei) {
    if (threadIdx.x == 0) {
        int ok = 1;
        for (int k = 0; k < 64; k++) {
            long long v = ei[k];
            if (v < 0 || v >= NN) { ok = 0; break; }
        }
        g_is64 = ok;
    }
}

// ---------------- convert + count + rank (2 edges/thread) ------------------
__global__ void convert_count_kernel(const long long* __restrict__ ei) {
    int e = (blockIdx.x * blockDim.x + threadIdx.x) * 2;
    if (e >= EE) return;
    int s0, s1, d0, d1;
    if (g_is64) {
        longlong2 sv = *(const longlong2*)&ei[e];
        longlong2 dv = *(const longlong2*)&ei[e + EE];
        s0 = (int)sv.x; s1 = (int)sv.y; d0 = (int)dv.x; d1 = (int)dv.y;
    } else {
        const int* p = (const int*)ei;
        int2 sv = *(const int2*)&p[e];
        int2 dv = *(const int2*)&p[e + EE];
        s0 = sv.x; s1 = sv.y; d0 = dv.x; d1 = dv.y;
    }
    *(int2*)&g_src[e] = make_int2(s0, s1);
    *(int2*)&g_dst[e] = make_int2(d0, d1);
    int r0 = atomicAdd(&g_cnt[d0], 1);
    int r1 = atomicAdd(&g_cnt[d1], 1);
    *(int2*)&g_rank[e] = make_int2(r0, r1);
}

// ---------------- scan phase 1: per-block exclusive scan -------------------
__global__ void scan1_kernel() {
    __shared__ int wsum[32];
    int t = threadIdx.x;
    int i = blockIdx.x * 1024 + t;
    int v = (i < NN) ? g_cnt[i] : 0;
    int lane = t & 31, wid = t >> 5;
    int p = v;
    #pragma unroll
    for (int off = 1; off < 32; off <<= 1) {
        int a = __shfl_up_sync(FULLM, p, off);
        if (lane >= off) p += a;
    }
    if (lane == 31) wsum[wid] = p;
    __syncthreads();
    if (wid == 0) {
        int s = wsum[lane];
        #pragma unroll
        for (int off = 1; off < 32; off <<= 1) {
            int a = __shfl_up_sync(FULLM, s, off);
            if (lane >= off) s += a;
        }
        wsum[lane] = s;
    }
    __syncthreads();
    int base = (wid > 0) ? wsum[wid - 1] : 0;
    int incl = p + base;
    if (i < NN) g_indptr[i] = incl - v;      // exclusive within block
    if (t == 1023) g_bsum[blockIdx.x] = incl;
}

// ---------------- scan phase 2+3 merged ------------------------------------
__global__ void scan23_kernel() {
    int i = blockIdx.x * blockDim.x + threadIdx.x;
    int j = (int)((blockIdx.x * blockDim.x) >> 10);
    int lane = threadIdx.x & 31;
    int acc = 0;
    for (int k = lane; k < j; k += 32) acc += g_bsum[k];
    #pragma unroll
    for (int off = 16; off > 0; off >>= 1)
        acc += __shfl_xor_sync(FULLM, acc, off);
    if (i < NN) g_indptr[i] += acc;
    if (i == 0) g_indptr[NN] = EE;
}

// ---------------- CSR scatter: 2 edges/thread, rank precomputed ------------
__global__ void scatter_kernel() {
    int e = (blockIdx.x * blockDim.x + threadIdx.x) * 2;
    if (e >= EE) return;
    int2 s = *(const int2*)&g_src[e];
    int2 d = *(const int2*)&g_dst[e];
    int2 r = *(const int2*)&g_rank[e];
    g_indices[g_indptr[d.x] + r.x] = s.x;
    g_indices[g_indptr[d.y] + r.y] = s.y;
}

// ---------------- GEMM1 (smem W, chunked xs, packed FFMA2) + als1/ald1 -----
__global__ __launch_bounds__(256, 4)
void gemm1_kernel(const float* __restrict__ x, const float* __restrict__ W,
                  const float* __restrict__ a_src, const float* __restrict__ a_dst) {
    extern __shared__ float sm[];
    float* ws = sm;                         // [128][64]
    float* xs = sm + DIN * HD;              // [128][XS_STRIDE]
    int t = threadIdx.x;
    int bn = blockIdx.x * 128;
    for (int i = t; i < DIN * HD / 4; i += 256)
        ((float4*)ws)[i] = ((const float4*)W)[i];

    int colq = t & 7;
    int nr   = t >> 3;
    u64 accA[4][2], accB[4][2];
    #pragma unroll
    for (int i = 0; i < 4; i++) {
        accA[i][0] = accA[i][1] = 0ULL;
        accB[i][0] = accB[i][1] = 0ULL;
    }
    for (int kc = 0; kc < DIN; kc += KC) {
        __syncthreads();
        #pragma unroll
        for (int i = t; i < 128 * 8; i += 256) {
            int r = i >> 3, c = i & 7;
            int node = bn + r;
            float4 v = (node < NN)
                ? *(const float4*)&x[(size_t)node * DIN + kc + c * 4]
                : make_float4(0.f, 0.f, 0.f, 0.f);
            *(float4*)&xs[r * XS_STRIDE + c * 4] = v;
        }
        __syncthreads();
        #pragma unroll 8
        for (int kk = 0; kk < KC; kk++) {
            ulonglong2 wa = *(const ulonglong2*)&ws[(kc + kk) * HD + colq * 4];
            ulonglong2 wb = *(const ulonglong2*)&ws[(kc + kk) * HD + 32 + colq * 4];
            float x0 = xs[nr * XS_STRIDE + kk];
            float x1 = xs[(nr + 32) * XS_STRIDE + kk];
            float x2 = xs[(nr + 64) * XS_STRIDE + kk];
            float x3 = xs[(nr + 96) * XS_STRIDE + kk];
            u64 X0 = packf2(x0, x0), X1 = packf2(x1, x1);
            u64 X2 = packf2(x2, x2), X3 = packf2(x3, x3);
            ffma2(accA[0][0], X0, wa.x); ffma2(accA[0][1], X0, wa.y);
            ffma2(accB[0][0], X0, wb.x); ffma2(accB[0][1], X0, wb.y);
            ffma2(accA[1][0], X1, wa.x); ffma2(accA[1][1], X1, wa.y);
            ffma2(accB[1][0], X1, wb.x); ffma2(accB[1][1], X1, wb.y);
            ffma2(accA[2][0], X2, wa.x); ffma2(accA[2][1], X2, wa.y);
            ffma2(accB[2][0], X2, wb.x); ffma2(accB[2][1], X2, wb.y);
            ffma2(accA[3][0], X3, wa.x); ffma2(accA[3][1], X3, wa.y);
            ffma2(accB[3][0], X3, wb.x); ffma2(accB[3][1], X3, wb.y);
        }
    }
    int hA = colq >> 2;
    int hB = 2 + hA;
    int woff = (colq & 3) * 4;
    float4 sA = *(const float4*)&a_src[hA * HID + woff];
    float4 dA = *(const float4*)&a_dst[hA * HID + woff];
    float4 sB = *(const float4*)&a_src[hB * HID + woff];
    float4 dB = *(const float4*)&a_dst[hB * HID + woff];
    #pragma unroll
    for (int i = 0; i < 4; i++) {
        int node = bn + nr + i * 32;
        bool ok = node < NN;
        float2 a01 = unpackf2(accA[i][0]);
        float2 a23 = unpackf2(accA[i][1]);
        float2 b01 = unpackf2(accB[i][0]);
        float2 b23 = unpackf2(accB[i][1]);
        if (ok) {
            __half2 pa0 = __floats2half2_rn(a01.x, a01.y);
            __half2 pa1 = __floats2half2_rn(a23.x, a23.y);
            __half2 pb0 = __floats2half2_rn(b01.x, b01.y);
            __half2 pb1 = __floats2half2_rn(b23.x, b23.y);
            *(uint2*)&g_h1h[(size_t)node * HD + colq * 4]      = make_uint2(*(unsigned*)&pa0, *(unsigned*)&pa1);
            *(uint2*)&g_h1h[(size_t)node * HD + 32 + colq * 4] = make_uint2(*(unsigned*)&pb0, *(unsigned*)&pb1);
        }
        float psA = a01.x*sA.x + a01.y*sA.y + a23.x*sA.z + a23.y*sA.w;
        float pdA = a01.x*dA.x + a01.y*dA.y + a23.x*dA.z + a23.y*dA.w;
        float psB = b01.x*sB.x + b01.y*sB.y + b23.x*sB.z + b23.y*sB.w;
        float pdB = b01.x*dB.x + b01.y*dB.y + b23.x*dB.z + b23.y*dB.w;
        #pragma unroll
        for (int off = 1; off < 4; off <<= 1) {
            psA += __shfl_xor_sync(FULLM, psA, off);
            pdA += __shfl_xor_sync(FULLM, pdA, off);
            psB += __shfl_xor_sync(FULLM, psB, off);
            pdB += __shfl_xor_sync(FULLM, pdB, off);
        }
        if (((colq & 3) == 0) && ok) {
            g_als1[node * 4 + hA] = psA;
            g_ald1[node * 4 + hA] = pdA;
            g_als1[node * 4 + hB] = psB;
            g_ald1[node * 4 + hB] = pdB;
        }
    }
}

// ---------------- FUSED gather1: half-warp edge pairing --------------------
// Warp per dst node. m = lane&15 covers channels 4m..4m+3 (head m>>2, uint2 of
// halves); le = lane>>4 selects edge parity -> 2 edges per LDG issue.
__global__ void gather1_fused_kernel(const float* __restrict__ b1,
                                     const float* __restrict__ W2,
                                     const float* __restrict__ a_src2,
                                     const float* __restrict__ a_dst2) {
    int n = (blockIdx.x * blockDim.x + threadIdx.x) >> 5;
    if (n >= NN) return;
    int lane = threadIdx.x & 31;
    int m = lane & 15, le = lane >> 4;
    int myh = m >> 2;
    float ad = g_ald1[n * 4 + myh];
    float4 acc = make_float4(0.f, 0.f, 0.f, 0.f);
    float z = 0.f;
    if (le == 0) {  // self loop counted once
        float w = lrelu_exp(g_als1[n * 4 + myh] + ad);
        z += w;
        uint2 u = *(const uint2*)&g_h1h[(size_t)n * HD + m * 4];
        float2 p0 = __half22float2(*(__half2*)&u.x);
        float2 p1 = __half22float2(*(__half2*)&u.y);
        acc.x += p0.x * w; acc.y += p0.y * w; acc.z += p1.x * w; acc.w += p1.y * w;
    }
    int e = g_indptr[n], end = g_indptr[n + 1];
    for (; e + 8 <= end; e += 8) {
        int s0 = g_indices[e + 0 + le];
        int s1 = g_indices[e + 2 + le];
        int s2 = g_indices[e + 4 + le];
        int s3 = g_indices[e + 6 + le];
        float l0 = g_als1[s0 * 4 + myh], l1 = g_als1[s1 * 4 + myh];
        float l2 = g_als1[s2 * 4 + myh], l3 = g_als1[s3 * 4 + myh];
        uint2 u0 = *(const uint2*)&g_h1h[(size_t)s0 * HD + m * 4];
        uint2 u1 = *(const uint2*)&g_h1h[(size_t)s1 * HD + m * 4];
        uint2 u2 = *(const uint2*)&g_h1h[(size_t)s2 * HD + m * 4];
        uint2 u3 = *(const uint2*)&g_h1h[(size_t)s3 * HD + m * 4];
        float w0 = lrelu_exp(l0 + ad), w1 = lrelu_exp(l1 + ad);
        float w2 = lrelu_exp(l2 + ad), w3 = lrelu_exp(l3 + ad);
        z += (w0 + w1) + (w2 + w3);
        float2 a0 = __half22float2(*(__half2*)&u0.x), b0 = __half22float2(*(__half2*)&u0.y);
        float2 a1 = __half22float2(*(__half2*)&u1.x), b1v = __half22float2(*(__half2*)&u1.y);
        float2 a2 = __half22float2(*(__half2*)&u2.x), b2v = __half22float2(*(__half2*)&u2.y);
        float2 a3 = __half22float2(*(__half2*)&u3.x), b3v = __half22float2(*(__half2*)&u3.y);
        acc.x += a0.x*w0 + a1.x*w1 + a2.x*w2 + a3.x*w3;
        acc.y += a0.y*w0 + a1.y*w1 + a2.y*w2 + a3.y*w3;
        acc.z += b0.x*w0 + b1v.x*w1 + b2v.x*w2 + b3v.x*w3;
        acc.w += b0.y*w0 + b1v.y*w1 + b2v.y*w2 + b3v.y*w3;
    }
    for (; e < end; e += 2) {
        bool valid = (e + le) < end;
        int s = valid ? g_indices[e + le] : 0;
        float l = g_als1[s * 4 + myh];
        uint2 u = *(const uint2*)&g_h1h[(size_t)s * HD + m * 4];
        float w = valid ? lrelu_exp(l + ad) : 0.f;
        z += w;
        float2 p0 = __half22float2(*(__half2*)&u.x);
        float2 p1 = __half22float2(*(__half2*)&u.y);
        acc.x += p0.x * w; acc.y += p0.y * w; acc.z += p1.x * w; acc.w += p1.y * w;
    }
    // combine the two half-warps
    acc.x += __shfl_xor_sync(FULLM, acc.x, 16);
    acc.y += __shfl_xor_sync(FULLM, acc.y, 16);
    acc.z += __shfl_xor_sync(FULLM, acc.z, 16);
    acc.w += __shfl_xor_sync(FULLM, acc.w, 16);
    z     += __shfl_xor_sync(FULLM, z, 16);
    float zi = 1.f / (z + 1e-16f);
    float4 bb = *(const float4*)&b1[m * 4];
    float f0 = acc.x * zi + bb.x;
    float f1 = acc.y * zi + bb.y;
    float f2 = acc.z * zi + bb.z;
    float f3 = acc.w * zi + bb.w;
    f0 = f0 > 0.f ? f0 : expm1f(f0);    // ELU
    f1 = f1 > 0.f ? f1 : expm1f(f1);
    f2 = f2 > 0.f ? f2 : expm1f(f2);
    f3 = f3 > 0.f ? f3 : expm1f(f3);
    // ---- fused GEMV: t = feat @ W2, lane computes output channel `lane` ----
    float t = 0.f;
    #pragma unroll
    for (int k = 0; k < 16; k++) {
        float g0 = __shfl_sync(FULLM, f0, k);
        float g1 = __shfl_sync(FULLM, f1, k);
        float g2 = __shfl_sync(FULLM, f2, k);
        float g3 = __shfl_sync(FULLM, f3, k);
        t += g0 * __ldg(&W2[(4 * k)     * DOUT + lane])
           + g1 * __ldg(&W2[(4 * k + 1) * DOUT + lane])
           + g2 * __ldg(&W2[(4 * k + 2) * DOUT + lane])
           + g3 * __ldg(&W2[(4 * k + 3) * DOUT + lane]);
    }
    g_t2h[(size_t)n * DOUT + lane] = __float2half_rn(t);
    // ---- fused als2/ald2 (fp32 exact) ----
    float ps = t * __ldg(&a_src2[lane]);
    float pd = t * __ldg(&a_dst2[lane]);
    #pragma unroll
    for (int off = 16; off > 0; off >>= 1) {
        ps += __shfl_xor_sync(FULLM, ps, off);
        pd += __shfl_xor_sync(FULLM, pd, off);
    }
    if (lane == 0) { g_als2[n] = ps; g_ald2[n] = pd; }
}

// ---------------- gather2: half-warp edge pairing, writes d_out ------------
// m = lane&15 covers channels 2m,2m+1 (half2); le = edge parity.
__global__ void gather2_kernel(float* __restrict__ out, const float* __restrict__ b2) {
    int n = (blockIdx.x * blockDim.x + threadIdx.x) >> 5;
    if (n >= NN) return;
    int lane = threadIdx.x & 31;
    int m = lane & 15, le = lane >> 4;
    float ad = g_ald2[n];
    float accx = 0.f, accy = 0.f, z = 0.f;
    if (le == 0) {  // self loop counted once
        float w = lrelu_exp(g_als2[n] + ad);
        z += w;
        float2 v = __half22float2(*(const __half2*)&g_t2h[(size_t)n * DOUT + m * 2]);
        accx += v.x * w; accy += v.y * w;
    }
    int e = g_indptr[n], end = g_indptr[n + 1];
    for (; e + 8 <= end; e += 8) {
        int s0 = g_indices[e + 0 + le];
        int s1 = g_indices[e + 2 + le];
        int s2 = g_indices[e + 4 + le];
        int s3 = g_indices[e + 6 + le];
        float l0 = g_als2[s0], l1 = g_als2[s1], l2 = g_als2[s2], l3 = g_als2[s3];
        __half2 u0 = *(const __half2*)&g_t2h[(size_t)s0 * DOUT + m * 2];
        __half2 u1 = *(const __half2*)&g_t2h[(size_t)s1 * DOUT + m * 2];
        __half2 u2 = *(const __half2*)&g_t2h[(size_t)s2 * DOUT + m * 2];
        __half2 u3 = *(const __half2*)&g_t2h[(size_t)s3 * DOUT + m * 2];
        float w0 = lrelu_exp(l0 + ad), w1 = lrelu_exp(l1 + ad);
        float w2 = lrelu_exp(l2 + ad), w3 = lrelu_exp(l3 + ad);
        z += (w0 + w1) + (w2 + w3);
        float2 v0 = __half22float2(u0), v1 = __half22float2(u1);
        float2 v2 = __half22float2(u2), v3 = __half22float2(u3);
        accx += v0.x*w0 + v1.x*w1 + v2.x*w2 + v3.x*w3;
        accy += v0.y*w0 + v1.y*w1 + v2.y*w2 + v3.y*w3;
    }
    for (; e < end; e += 2) {
        bool valid = (e + le) < end;
        int s = valid ? g_indices[e + le] : 0;
        float l = g_als2[s];
        __half2 u = *(const __half2*)&g_t2h[(size_t)s * DOUT + m * 2];
        float w = valid ? lrelu_exp(l + ad) : 0.f;
        z += w;
        float2 v = __half22float2(u);
        accx += v.x * w; accy += v.y * w;
    }
    accx += __shfl_xor_sync(FULLM, accx, 16);
    accy += __shfl_xor_sync(FULLM, accy, 16);
    z    += __shfl_xor_sync(FULLM, z, 16);
    if (le == 0) {
        float zi = 1.f / (z + 1e-16f);
        float2 bb = *(const float2*)&b2[m * 2];
        *(float2*)&out[(size_t)n * DOUT + m * 2] =
            make_float2(accx * zi + bb.x, accy * zi + bb.y);
    }
}

// ---------------------------------------------------------------------------
extern "C" void kernel_launch(void* const* d_in, const int* in_sizes, int n_in,
                              void* d_out, int out_size) {
    const float*     x      = (const float*)d_in[0];
    const long long* ei     = (const long long*)d_in[1];
    const float*     W1     = (const float*)d_in[2];
    const float*     a_src1 = (const float*)d_in[3];
    const float*     a_dst1 = (const float*)d_in[4];
    const float*     b1     = (const float*)d_in[5];
    const float*     W2     = (const float*)d_in[6];
    const float*     a_src2 = (const float*)d_in[7];
    const float*     a_dst2 = (const float*)d_in[8];
    const float*     b2     = (const float*)d_in[9];
    float* out = (float*)d_out;

    const int NB = (NN + 255) / 256;
    const int GB = (NN + 127) / 128;
    const int E2 = (EE / 2 + 255) / 256;
    const int WB = (NN * 32 + 255) / 256;

    // zero degree counters via memset node (not a kernel launch)
    void* cntPtr = nullptr;
    cudaGetSymbolAddress(&cntPtr, g_cnt);
    cudaMemsetAsync(cntPtr, 0, NN * sizeof(int), 0);

    cudaEventRecord(g_evFork, 0);
    cudaStreamWaitEvent(g_s2, g_evFork, 0);

    detect_kernel<<<1, 32>>>(ei);
    convert_count_kernel<<<E2, 256>>>(ei);
    scan1_kernel<<<NBLK, 1024>>>();
    gemm1_kernel<<<GB, 256, G1_SMEM, g_s2>>>(x, W1, a_src1, a_dst1);
    cudaEventRecord(g_evJoin, g_s2);
    scan23_kernel<<<NB, 256>>>();
    scatter_kernel<<<E2, 256>>>();

    cudaStreamWaitEvent(0, g_evJoin, 0);
    gather1_fused_kernel<<<WB, 256>>>(b1, W2, a_src2, a_dst2);
    gather2_kernel<<<WB, 256>>>(out, b2);
}